// round 7
// baseline (speedup 1.0000x reference)
#include <cuda_runtime.h>

// Problem constants
#define CTC_B 256
#define CTC_T 256
#define CTC_C 512
#define CTC_L 64
#define ROWE  66            // g_emit floats per row: 64 label log2-probs + blank + pad
#define NEGV  (-1e30f)
#define LOG2E 1.4426950408889634f
#define LN2   0.6931471805599453f
#define DPCH  8             // DP prefetch chunk (rows)
#define NCH   (CTC_T / DPCH)

__device__ float g_emit[(size_t)CTC_B * CTC_T * ROWE];   // log2-probs (~17 MB)
__device__ float g_nll[CTC_B];
__device__ unsigned int g_count = 0;

__device__ __forceinline__ float warpsum(float v) {
#pragma unroll
    for (int o = 16; o; o >>= 1) v += __shfl_xor_sync(0xffffffffu, v, o);
    return v;
}

// logaddexp in log2 domain (validated in R2/R3: rel_err ~8e-8)
__device__ __forceinline__ float lae2_2(float x, float y) {
    float m = fmaxf(x, y);
    float d = fminf(x, y) - m;
    return m + __log2f(1.0f + exp2f(d));
}
__device__ __forceinline__ float lae2_3(float x, float y, float z) {
    float m = fmaxf(fmaxf(x, y), z);
    float s = exp2f(x - m) + exp2f(y - m) + exp2f(z - m);
    return m + __log2f(s);
}

// Kernel 1: per (b,t) row: log2-softmax over C=512, write the 65 needed
// symbols (64 label slots + blank) to g_emit. One warp per row, 8 rows/block.
__global__ void __launch_bounds__(256) lse_emit_kernel(
    const float* __restrict__ logits, const int* __restrict__ labels)
{
    __shared__ float srow[8][CTC_C];
    __shared__ int   slab[CTC_L];
    const int w    = threadIdx.x >> 5;
    const int lane = threadIdx.x & 31;
    const int row_id = blockIdx.x * 8 + w;          // = b*T + t
    const int b = blockIdx.x >> 5;                  // 32 blocks per batch

    if (threadIdx.x < CTC_L) slab[threadIdx.x] = labels[b * CTC_L + threadIdx.x];

    const float4* row4 = (const float4*)(logits + (size_t)row_id * CTC_C);
    float4 v[4];
#pragma unroll
    for (int k = 0; k < 4; k++) v[k] = row4[k * 32 + lane];

    // Unshifted exp-sum in log2 domain (logits are O(1): no overflow risk).
    float s = 0.f;
#pragma unroll
    for (int k = 0; k < 4; k++) {
        const float e0 = exp2f(v[k].x * LOG2E);
        const float e1 = exp2f(v[k].y * LOG2E);
        const float e2 = exp2f(v[k].z * LOG2E);
        const float e3 = exp2f(v[k].w * LOG2E);
        const int i4 = (k * 32 + lane) * 4;
        srow[w][i4 + 0] = v[k].x; srow[w][i4 + 1] = v[k].y;
        srow[w][i4 + 2] = v[k].z; srow[w][i4 + 3] = v[k].w;
        s += e0 + e1 + e2 + e3;
    }
    s = warpsum(s);
    const float lse2 = __log2f(s);      // log2-sum-exp of the row
    __syncthreads();                    // srow + slab visibility

    float* eout = g_emit + (size_t)row_id * ROWE;
    eout[lane]      = fmaf(srow[w][slab[lane]],      LOG2E, -lse2);
    eout[32 + lane] = fmaf(srow[w][slab[32 + lane]], LOG2E, -lse2);
    if (lane == 0)
        eout[CTC_L] = fmaf(srow[w][CTC_C - 1], LOG2E, -lse2);   // blank
}

// Kernel 2: CTC forward DP in log2 domain, one warp per batch element.
// Lane l owns states s = 4l+j (j=0..3); lane 31 additionally s=128.
// 8-row register double-buffered prefetch hides L2 latency.
__global__ void __launch_bounds__(32) ctc_dp_kernel(
    const int* __restrict__ labels,
    const int* __restrict__ label_length,
    const int* __restrict__ logit_length,
    float* __restrict__ out)
{
    __shared__ int slab[CTC_L];
    const int b    = blockIdx.x;
    const int lane = threadIdx.x;

    slab[lane]      = labels[b * CTC_L + lane];
    slab[32 + lane] = labels[b * CTC_L + 32 + lane];
    __syncwarp();

    const int tl = logit_length[b];
    const int ll = label_length[b];
    const int tlm1 = tl - 1;

    // skip allowed (odd states only): s=4l+1 sym=2l ; s=4l+3 sym=2l+1
    const bool skip1 = ((4 * lane + 1) >= 3) && (slab[2 * lane] != slab[2 * lane - 1]);
    const bool skip3 = (slab[2 * lane + 1] != slab[2 * lane]);

    const float* ebase = g_emit + (size_t)b * CTC_T * ROWE;

    float2 e2A[DPCH], e2B[DPCH];
    float  ebA[DPCH], ebB[DPCH];

    auto load_chunk = [&](int c, float2* e2, float* eb) {
#pragma unroll
        for (int j = 0; j < DPCH; j++) {
            const float* r = ebase + (size_t)(c * DPCH + j) * ROWE;
            e2[j] = __ldg((const float2*)r + lane);   // log2-probs syms 2l, 2l+1
            eb[j] = __ldg(r + CTC_L);                 // blank log2-prob
        }
    };

    float a0 = NEGV, a1 = NEGV, a2 = NEGV, a3 = NEGV, a4 = NEGV;
    float s0 = NEGV, s1 = NEGV, s2 = NEGV, s3 = NEGV, s4 = NEGV;

    auto compute_chunk = [&](int c, const float2* e2, const float* eb) {
#pragma unroll
        for (int j = 0; j < DPCH; j++) {
            const int t = c * DPCH + j;
            if (t == 0) {
                a0 = (lane == 0) ? eb[0]   : NEGV;    // s=0 (blank)
                a1 = (lane == 0) ? e2[0].x : NEGV;    // s=1 (label 0)
                a2 = NEGV; a3 = NEGV; a4 = NEGV;
            } else {
                float am1 = __shfl_up_sync(0xffffffffu, a3, 1);  // alpha[4l-1]
                if (lane == 0) am1 = NEGV;
                const float na0 = lae2_2(a0, am1)                        + eb[j];
                const float na1 = lae2_3(a1, a0, skip1 ? am1  : NEGV)    + e2[j].x;
                const float na2 = lae2_2(a2, a1)                         + eb[j];
                const float na3 = lae2_3(a3, a2, skip3 ? a1 : NEGV)      + e2[j].y;
                const float na4 = lae2_2(a4, a3)                         + eb[j];
                a0 = na0; a1 = na1; a2 = na2; a3 = na3; a4 = na4;
            }
            if (t == tlm1) { s0 = a0; s1 = a1; s2 = a2; s3 = a3; s4 = a4; }
        }
    };

    load_chunk(0, e2A, ebA);
#pragma unroll 2
    for (int c = 0; c < NCH; c++) {
        if (c & 1) {
            if (c + 1 < NCH) load_chunk(c + 1, e2A, ebA);
            compute_chunk(c, e2B, ebB);
        } else {
            if (c + 1 < NCH) load_chunk(c + 1, e2B, ebB);
            compute_chunk(c, e2A, ebA);
        }
    }

    // -------- finalize --------
    const int se = 2 * ll;              // final blank state
    const int sm = se - 1;
    const int ie = (se >> 2) & 31;
    const int im = (sm >> 2) & 31;
    const float t0 = __shfl_sync(0xffffffffu, s0, ie);
    const float t1 = __shfl_sync(0xffffffffu, s1, ie);
    const float t2 = __shfl_sync(0xffffffffu, s2, ie);
    const float t3 = __shfl_sync(0xffffffffu, s3, ie);
    const float t4 = __shfl_sync(0xffffffffu, s4, 31);
    const float u0 = __shfl_sync(0xffffffffu, s0, im);
    const float u1 = __shfl_sync(0xffffffffu, s1, im);
    const float u2 = __shfl_sync(0xffffffffu, s2, im);
    const float u3 = __shfl_sync(0xffffffffu, s3, im);

    unsigned done = 0;
    if (lane == 0) {
        const int je = se & 3;
        const float v_end = (se >= 128) ? t4
                          : (je == 0 ? t0 : je == 1 ? t1 : je == 2 ? t2 : t3);
        const int jm = sm & 3;
        const float v_m1 = (jm == 0 ? u0 : jm == 1 ? u1 : jm == 2 ? u2 : u3);
        g_nll[b] = -LN2 * lae2_2(v_end, v_m1);       // back to natural log
        __threadfence();
        done = (atomicAdd(&g_count, 1u) == CTC_B - 1) ? 1u : 0u;
    }
    done = __shfl_sync(0xffffffffu, done, 0);
    if (done) {
        // last-finishing block: deterministic fixed-tree mean
        float s = 0.f;
#pragma unroll
        for (int i = 0; i < CTC_B / 32; i++)
            s += __ldcg(&g_nll[i * 32 + lane]);
        s = warpsum(s);
        if (lane == 0) {
            out[0] = s * (1.0f / CTC_B);
            g_count = 0;                 // reset for next graph replay
        }
    }
}

extern "C" void kernel_launch(void* const* d_in, const int* in_sizes, int n_in,
                              void* d_out, int out_size)
{
    const float* logits       = (const float*)d_in[0];
    const int*   labels       = (const int*)d_in[1];
    const int*   label_length = (const int*)d_in[2];
    const int*   logit_length = (const int*)d_in[3];

    lse_emit_kernel<<<(CTC_B * CTC_T) / 8, 256>>>(logits, labels);
    ctc_dp_kernel<<<CTC_B, 32>>>(labels, label_length, logit_length, (float*)d_out);
    (void)in_sizes; (void)n_in; (void)out_size;
}